// round 8
// baseline (speedup 1.0000x reference)
#include <cuda_runtime.h>
#include <cstdint>

#define T_STEPS 800
#define B_DIM   128
#define S_DIM   500
#define M_DIM   (T_STEPS * B_DIM)   /* 102400 */
#define BS      (B_DIM * S_DIM)     /* 64000  */

// Scratch: total[t,b,s] = input - err @ W^T   (204.8 MB, static device global)
__device__ float g_total[(size_t)M_DIM * S_DIM];

// ---------------------------------------------------------------------------
// Shared-memory layout (dynamic):
//   As2: [2][16][130] u64  (duplicated {a,a} pairs, stride 130 for bank spread)
//   Bs : [2][16][128] f32
// ---------------------------------------------------------------------------
#define AS_STRIDE 130
#define AS_BYTES  (2 * 16 * AS_STRIDE * 8)          /* 33280 */
#define SMEM_DYN  (AS_BYTES + 2 * 16 * 128 * 4)     /* 49664 */

__device__ __forceinline__ void ffma2(unsigned long long& c,
                                      unsigned long long a,
                                      unsigned long long b) {
    // packed 2x fp32 IEEE-RN fma (sm_100+ base ISA)
    asm("fma.rn.f32x2 %0, %1, %2, %0;" : "+l"(c) : "l"(a), "l"(b));
}
__device__ __forceinline__ unsigned long long dup32(float v) {
    const unsigned u = __float_as_uint(v);
    return (unsigned long long)u | ((unsigned long long)u << 32);
}
__device__ __forceinline__ float lo32(unsigned long long v) {
    return __uint_as_float((unsigned)v);
}
__device__ __forceinline__ float hi32(unsigned long long v) {
    return __uint_as_float((unsigned)(v >> 32));
}

// ---------------------------------------------------------------------------
// GEMM: g_total[M,N] = input - err[M,K] * W[N,K]^T   (M=102400, N=K=500)
// Round-1 structure (proven correct, bit-identical arithmetic order), inner
// product packed into fma.rn.f32x2 (acc pairs along n).
// ---------------------------------------------------------------------------
__global__ __launch_bounds__(256, 2) void gemm_f32x2(
    const float* __restrict__ input,
    const float* __restrict__ err,
    const float* __restrict__ W)
{
    extern __shared__ __align__(16) char smem[];
    unsigned long long* As2 = (unsigned long long*)smem;       // [2][16][AS_STRIDE]
    float*              Bs  = (float*)(smem + AS_BYTES);       // [2][16][128]

    const int K  = S_DIM;
    const int N  = S_DIM;
    const int BK = 16;
    const int KT = (K + BK - 1) / BK;   // 32 k-tiles (last has 4 valid cols)

    const int tid = threadIdx.x;
    const int m0  = blockIdx.y * 128;
    const int n0  = blockIdx.x * 128;

    // global-load mapping: each thread loads 2 float4 of A and 2 float4 of B
    const int lrow = tid >> 2;          // 0..63
    const int lcol = (tid & 3) << 2;    // 0,4,8,12

    const float* aptr0 = err + (size_t)(m0 + lrow) * K + lcol;
    const float* aptr1 = aptr0 + (size_t)64 * K;
    const int nr0 = n0 + lrow;
    const int nr1 = n0 + lrow + 64;
    const float* bptr0 = W + (size_t)nr0 * K + lcol;
    const float* bptr1 = W + (size_t)nr1 * K + lcol;

    float4 pa0, pa1, pb0, pb1;
    const float4 f4z = make_float4(0.f, 0.f, 0.f, 0.f);

    auto LOADG = [&](int kt) {
        const int k0 = kt * BK;
        const bool kok = (k0 + lcol + 4 <= K);
        pa0 = kok ? *(const float4*)(aptr0 + k0) : f4z;
        pa1 = kok ? *(const float4*)(aptr1 + k0) : f4z;
        pb0 = (kok && nr0 < N) ? *(const float4*)(bptr0 + k0) : f4z;
        pb1 = (kok && nr1 < N) ? *(const float4*)(bptr1 + k0) : f4z;
    };
    auto STOS = [&](int buf) {
        unsigned long long* Ab = As2 + (size_t)buf * 16 * AS_STRIDE;
        float* Bb = Bs + (size_t)buf * 16 * 128;
#pragma unroll
        for (int j = 0; j < 4; ++j) {
            const float aj0 = (&pa0.x)[j];
            const float aj1 = (&pa1.x)[j];
            Ab[(lcol + j) * AS_STRIDE + lrow]      = dup32(aj0);
            Ab[(lcol + j) * AS_STRIDE + lrow + 64] = dup32(aj1);
            Bb[(lcol + j) * 128 + lrow]      = (&pb0.x)[j];
            Bb[(lcol + j) * 128 + lrow + 64] = (&pb1.x)[j];
        }
    };

    const int tx = tid & 15;   // n-dir, 8 cols each
    const int ty = tid >> 4;   // m-dir, 8 rows each

    unsigned long long acc[8][4];
#pragma unroll
    for (int i = 0; i < 8; ++i)
#pragma unroll
        for (int jp = 0; jp < 4; ++jp) acc[i][jp] = 0ull;

    LOADG(0);
    STOS(0);
    __syncthreads();

    for (int kt = 0; kt < KT; ++kt) {
        const int buf = kt & 1;
        if (kt + 1 < KT) LOADG(kt + 1);

        const unsigned long long* Ab = As2 + (size_t)buf * 16 * AS_STRIDE + ty * 8;
        const float* Bb = Bs + (size_t)buf * 16 * 128 + tx * 8;

#pragma unroll
        for (int kk = 0; kk < BK; ++kk) {
            const unsigned long long* ar = Ab + kk * AS_STRIDE;
            ulonglong2 a01 = *(const ulonglong2*)(ar + 0);
            ulonglong2 a23 = *(const ulonglong2*)(ar + 2);
            ulonglong2 a45 = *(const ulonglong2*)(ar + 4);
            ulonglong2 a67 = *(const ulonglong2*)(ar + 6);
            const float* br = Bb + kk * 128;
            ulonglong2 b01 = *(const ulonglong2*)(br + 0);
            ulonglong2 b23 = *(const ulonglong2*)(br + 4);

            const unsigned long long A[8] = {a01.x, a01.y, a23.x, a23.y,
                                             a45.x, a45.y, a67.x, a67.y};
            const unsigned long long Bv[4] = {b01.x, b01.y, b23.x, b23.y};
#pragma unroll
            for (int i = 0; i < 8; ++i)
#pragma unroll
                for (int jp = 0; jp < 4; ++jp)
                    ffma2(acc[i][jp], A[i], Bv[jp]);
        }

        if (kt + 1 < KT) STOS(buf ^ 1);
        __syncthreads();
    }

    // Epilogue: g_total = input - acc   (same arithmetic order as round 1)
#pragma unroll
    for (int i = 0; i < 8; ++i) {
        const int m = m0 + ty * 8 + i;
        const float* inrow = input + (size_t)m * N;
        float* orow = g_total + (size_t)m * N;
#pragma unroll
        for (int jv = 0; jv < 2; ++jv) {
            const int n = n0 + tx * 8 + jv * 4;
            const float c0 = lo32(acc[i][jv * 2 + 0]);
            const float c1 = hi32(acc[i][jv * 2 + 0]);
            const float c2 = lo32(acc[i][jv * 2 + 1]);
            const float c3 = hi32(acc[i][jv * 2 + 1]);
            if (n + 4 <= N) {
                float4 iv = *(const float4*)(inrow + n);
                float4 ov;
                ov.x = iv.x - c0;
                ov.y = iv.y - c1;
                ov.z = iv.z - c2;
                ov.w = iv.w - c3;
                *(float4*)(orow + n) = ov;
            } else {
                const float cc[4] = {c0, c1, c2, c3};
#pragma unroll
                for (int jj = 0; jj < 4; ++jj)
                    if (n + jj < N)
                        orow[n + jj] = inrow[n + jj] - cc[jj];
            }
        }
    }
}

// ---------------------------------------------------------------------------
// Scan (round-1 verbatim): one thread per (b,s) lane, 800 steps.
// ---------------------------------------------------------------------------
__global__ __launch_bounds__(256) void scan_kernel(
    float* __restrict__ spks, float* __restrict__ traces)
{
    const int i = blockIdx.x * 256 + threadIdx.x;
    if (i >= BS) return;

    const float ALPHA  = (float)(1.0 - 0.25 / 10.0);
    const float BETA   = (float)(1.0 - 0.25 / 20.0);
    const float KAPPA  = (float)(1.0 - 0.25 / 30.0);
    const float THRESH = 0.4f;

    float syn = 0.f, mem = 0.f, tr = 0.f;
    const float* p  = g_total + i;
    float* ps = spks + i;
    float* pt = traces + i;

#pragma unroll 4
    for (int t = 0; t < T_STEPS; ++t) {
        const float tot = __ldg(p + (size_t)t * BS);
        const float reset = (mem - THRESH) > 0.f ? 1.f : 0.f;
        syn = ALPHA * syn + tot;
        mem = (BETA * mem + syn) * (1.f - reset);
        const float spk = (mem - THRESH) > 0.f ? 1.f : 0.f;
        tr = KAPPA * tr + spk;
        ps[(size_t)t * BS] = spk;
        pt[(size_t)t * BS] = tr;
    }
}

// ---------------------------------------------------------------------------
extern "C" void kernel_launch(void* const* d_in, const int* in_sizes, int n_in,
                              void* d_out, int out_size)
{
    const float* input = (const float*)d_in[0];   // (T,B,S)
    const float* err   = (const float*)d_in[1];   // (T,B,S)
    const float* W     = (const float*)d_in[2];   // (S,S)
    float* out = (float*)d_out;                   // [spks | traces]

    cudaFuncSetAttribute(gemm_f32x2, cudaFuncAttributeMaxDynamicSharedMemorySize, SMEM_DYN);

    dim3 grid((S_DIM + 127) / 128, M_DIM / 128);  // (4, 800)
    gemm_f32x2<<<grid, 256, SMEM_DYN>>>(input, err, W);

    scan_kernel<<<(BS + 255) / 256, 256>>>(out, out + (size_t)T_STEPS * BS);
}